// round 13
// baseline (speedup 1.0000x reference)
#include <cuda_runtime.h>
#include <cuda_fp16.h>
#include <cstdint>
#include <cstddef>

// FusedAGGemm via mma.sync fp16 (HMMA m16n8k16, fp32 accum), round 13.
// R12 base + (a) single __syncthreads per iteration (R9-proven order),
// (b) warp-staggered k16 order to spread LDSM bursts across the smem
// crossbar. Zero added register pressure.
//   C[M,N] = sum_r A_r[M,KLOC] @ W[r*KLOC:(r+1)*KLOC] + bias

#define MDIM 4096
#define KLOC 1024
#define KDIM 8192
#define NDIM 1024

#define BM 128
#define BN 128
#define BK 64
#define NTH 256
#define NTILES (KDIM / BK)    // 128
#define NSTAGE 3

#define SWZ(o) ((o) ^ (((o) >> 3) & 0x70))
#define STAGE_BYTES 32768
#define SM_A(s) ((s) * STAGE_BYTES)
#define SM_B(s) ((s) * STAGE_BYTES + 16384)
#define SMEM_TOTAL (NSTAGE * STAGE_BYTES)   // 98304

__device__ __half g_At[(size_t)MDIM * KDIM];   // 64 MB, gathered fp16
__device__ __half g_Wt[(size_t)NDIM * KDIM];   // 16 MB, W^T fp16

// ---------------- helpers ----------------
__device__ __forceinline__ uint32_t smem_u32(const void* p) {
    uint32_t a;
    asm("{ .reg .u64 t; cvta.to.shared.u64 t, %1; cvt.u32.u64 %0, t; }"
        : "=r"(a) : "l"(p));
    return a;
}
__device__ __forceinline__ uint32_t f16x2(float lo, float hi) {
    uint32_t r;
    asm("cvt.rn.f16x2.f32 %0, %2, %1;" : "=r"(r) : "f"(lo), "f"(hi));
    return r;
}
__device__ __forceinline__ void cp_async16(uint32_t dst, const void* src) {
    asm volatile("cp.async.cg.shared.global [%0], [%1], 16;"
                 :: "r"(dst), "l"(src) : "memory");
}
__device__ __forceinline__ void ldsm4(uint32_t addr, uint32_t* r) {
    asm volatile("ldmatrix.sync.aligned.m8n8.x4.shared.b16 {%0,%1,%2,%3}, [%4];"
                 : "=r"(r[0]), "=r"(r[1]), "=r"(r[2]), "=r"(r[3]) : "r"(addr));
}
__device__ __forceinline__ void mma_f16(float* c, const uint32_t* a,
                                        uint32_t b0, uint32_t b1) {
    asm volatile(
        "mma.sync.aligned.m16n8k16.row.col.f32.f16.f16.f32 "
        "{%0,%1,%2,%3}, {%4,%5,%6,%7}, {%8,%9}, {%0,%1,%2,%3};"
        : "+f"(c[0]), "+f"(c[1]), "+f"(c[2]), "+f"(c[3])
        : "r"(a[0]), "r"(a[1]), "r"(a[2]), "r"(a[3]), "r"(b0), "r"(b1));
}

// ---------------- fused prepass ----------------
// blocks [0, 2048): A gather+convert, 32B-in / 16B-out per iteration.
// blocks [2048, 2048+8192): W transpose+convert (32x32 tiles).
__global__ void prep_all(const float* __restrict__ A, const float* __restrict__ W) {
    if (blockIdx.x < 2048) {
        const size_t n8 = (size_t)MDIM * KDIM / 8;
        for (size_t i = (size_t)blockIdx.x * blockDim.x + threadIdx.x; i < n8;
             i += (size_t)2048 * blockDim.x) {
            size_t m = i >> 10;
            size_t k = (i & 1023) << 3;
            size_t r = k >> 10, kk = k & (KLOC - 1);
            const float4* src = reinterpret_cast<const float4*>(
                A + ((r * MDIM + m) << 10) + kk);
            float4 v0 = src[0], v1 = src[1];
            uint4 o;
            o.x = f16x2(v0.x, v0.y);
            o.y = f16x2(v0.z, v0.w);
            o.z = f16x2(v1.x, v1.y);
            o.w = f16x2(v1.z, v1.w);
            *reinterpret_cast<uint4*>(&g_At[(m << 13) + k]) = o;
        }
    } else {
        __shared__ float t[32][33];
        const int b = blockIdx.x - 2048;
        const int n0 = (b & 31) * 32, k0 = (b >> 5) * 32;
        const int tx = threadIdx.x & 31, ty = (threadIdx.x >> 5) * 4;
        #pragma unroll
        for (int j = 0; j < 4; ++j)
            t[ty + j][tx] = W[(size_t)(k0 + ty + j) * NDIM + n0 + tx];
        __syncthreads();
        #pragma unroll
        for (int j = 0; j < 4; ++j)
            g_Wt[(size_t)(n0 + ty + j) * KDIM + k0 + tx] =
                __float2half_rn(t[tx][ty + j]);
    }
}

// ---------------- main GEMM ----------------
__global__ __launch_bounds__(NTH, 2)
void ag_gemm_mma(const float* __restrict__ bias, float* __restrict__ C)
{
    extern __shared__ char smem[];
    const uint32_t sb = smem_u32(smem);
    const int tid  = threadIdx.x;
    const int wid  = tid >> 5, lane = tid & 31;
    const int wm   = wid >> 2;          // 0..1 : warp m-half (64 rows)
    const int wn   = wid & 3;           // 0..3 : warp n-quarter (32 cols)
    const int m0   = blockIdx.y * BM;
    const int n0   = blockIdx.x * BN;
    const int kph  = wid & 3;           // k16 phase stagger per warp

    const uint32_t rowA = (uint32_t)(wm * 64 + (lane & 15));
    const uint32_t kA16 = (uint32_t)((lane >> 4) * 16);
    const uint32_t rowB = (uint32_t)(wn * 32 + (lane & 7) + ((lane >> 4) << 3));
    const uint32_t kB16 = (uint32_t)(((lane >> 3) & 1) * 16);

    float acc[4][4][4];
    #pragma unroll
    for (int i = 0; i < 4; ++i)
        #pragma unroll
        for (int j = 0; j < 4; ++j)
            #pragma unroll
            for (int q = 0; q < 4; ++q) acc[i][j][q] = 0.0f;

    const int grow = tid >> 3;          // 0..31
    const int gcol = tid & 7;           // 16B col group (8 fp16)

    auto issue_tile = [&](int kt, int s) {
        const __half* Ab = g_At + (size_t)(m0 + grow) * KDIM + kt * BK + gcol * 8;
        const __half* Bb = g_Wt + (size_t)(n0 + grow) * KDIM + kt * BK + gcol * 8;
        #pragma unroll
        for (int i = 0; i < 4; ++i) {
            uint32_t o = SWZ((uint32_t)(grow + 32 * i) * 128u + (uint32_t)gcol * 16u);
            cp_async16(sb + SM_A(s) + o, Ab + (size_t)i * 32 * KDIM);
            cp_async16(sb + SM_B(s) + o, Bb + (size_t)i * 32 * KDIM);
        }
        asm volatile("cp.async.commit_group;" ::: "memory");
    };

    auto compute_tile = [&](int s) {
        #pragma unroll
        for (int kk = 0; kk < 4; ++kk) {
            const int k16 = (kk + kph) & 3;    // staggered crossbar phase
            uint32_t a[4][4], b[2][4];
            #pragma unroll
            for (int i = 0; i < 4; ++i) {
                uint32_t o = (rowA + 16u * i) * 128u + (uint32_t)k16 * 32u + kA16;
                ldsm4(sb + SM_A(s) + SWZ(o), a[i]);
            }
            #pragma unroll
            for (int j = 0; j < 2; ++j) {
                uint32_t o = (rowB + 16u * j) * 128u + (uint32_t)k16 * 32u + kB16;
                ldsm4(sb + SM_B(s) + SWZ(o), b[j]);
            }
            #pragma unroll
            for (int i = 0; i < 4; ++i) {
                #pragma unroll
                for (int jj = 0; jj < 4; ++jj)
                    mma_f16(acc[i][jj], a[i],
                            b[jj >> 1][(jj & 1) * 2], b[jj >> 1][(jj & 1) * 2 + 1]);
            }
        }
    };

    // ---- 3-stage pipeline, ONE barrier per iteration ----
    issue_tile(0, 0);
    issue_tile(1, 1);

    for (int kt = 0; kt < NTILES; ++kt) {
        const int s = kt % NSTAGE;
        asm volatile("cp.async.wait_group 1;" ::: "memory");   // tile kt landed
        __syncthreads();   // tile kt visible to all + compute(kt-1) done
        if (kt + 2 < NTILES) issue_tile(kt + 2, (kt + 2) % NSTAGE);
        compute_tile(s);
    }

    // ---- epilogue: +bias (loaded here, not live through mainloop) ----
    const int er = lane >> 2;
    const int ec = (lane & 3) * 2;
    #pragma unroll
    for (int i = 0; i < 4; ++i) {
        const int gm = m0 + wm * 64 + i * 16 + er;
        #pragma unroll
        for (int jj = 0; jj < 4; ++jj) {
            const int gn = n0 + wn * 32 + jj * 8 + ec;
            const float bx = __ldg(bias + gn);
            const float by = __ldg(bias + gn + 1);
            float2 o0 = { acc[i][jj][0] + bx, acc[i][jj][1] + by };
            float2 o1 = { acc[i][jj][2] + bx, acc[i][jj][3] + by };
            *reinterpret_cast<float2*>(C + (size_t)gm * NDIM + gn) = o0;
            *reinterpret_cast<float2*>(C + (size_t)(gm + 8) * NDIM + gn) = o1;
        }
    }
}

extern "C" void kernel_launch(void* const* d_in, const int* in_sizes, int n_in,
                              void* d_out, int out_size)
{
    const float* all_act = (const float*)d_in[0];   // (8, 4096, 1024)
    const float* local_W = (const float*)d_in[1];   // (8192, 1024)
    const float* bias    = (const float*)d_in[2];   // (1024,)
    float* out = (float*)d_out;                     // (4096, 1024)

    prep_all<<<2048 + 8192, 256>>>(all_act, local_W);

    cudaFuncSetAttribute(ag_gemm_mma,
                         cudaFuncAttributeMaxDynamicSharedMemorySize, SMEM_TOTAL);
    dim3 grid(NDIM / BN, MDIM / BM);   // (8, 32) = 256 CTAs
    ag_gemm_mma<<<grid, NTH, SMEM_TOTAL>>>(bias, out);
}